// round 13
// baseline (speedup 1.0000x reference)
#include <cuda_runtime.h>
#include <math.h>
#include <float.h>

// Problem-fixed dims: N=8192, nin=256, nout=128
#define MAXN 8192
#define NIN  256
#define NOUT 128
#define NB   148      // persistent grid: 1 block/SM, co-resident
#define NT   1024

// Candidate window below global max M of hw2 (std ~181, Gumbel scale ~43).
// cnt ~ e^{160/43} ~ 43. A row is flagged only if it misses ALL ~17 nodes
// within 120 of M (P ~ 0.06 rows expected); flagged rows are recomputed
// exactly, warp-locally, inline. Dropped terms weigh <= e^-40 ~ 4e-18.
#define DELTA_CAND 160.0f
#define KEEP        40.0f

#define CAP        256    // candidate capacity (cnt>CAP -> all rows exact)
#define CAP_STAGE  128    // candidates staged in dynamic smem for accumulate

// -------- device scratch (no allocations allowed) --------
__device__ float    g_hw2[MAXN];
__device__ unsigned g_M_key;          // ordered-uint encoding of global max
__device__ float    g_hwC[(size_t)CAP * 4 * NOUT];  // quarter-K partials
__device__ unsigned g_bar_cnt;        // zero-init; reset by last block
__device__ unsigned g_done_cnt;

__device__ __forceinline__ unsigned fkey(float f) {
    unsigned b = __float_as_uint(f);
    return b ^ ((b >> 31) ? 0xFFFFFFFFu : 0x80000000u);
}
__device__ __forceinline__ float fkey_inv(unsigned k) {
    unsigned b = (k & 0x80000000u) ? (k ^ 0x80000000u) : ~k;
    return __uint_as_float(b);
}

// Software global barrier: thread 0 arrives + spins, block follows.
__device__ __forceinline__ void gbar(unsigned target) {
    __syncthreads();
    if (threadIdx.x == 0) {
        __threadfence();
        atomicAdd(&g_bar_cnt, 1u);
        while (*(volatile unsigned*)&g_bar_cnt < target) { }
        __threadfence();
    }
    __syncthreads();
}

// Warp-local EXACT recompute of one row (cold path; statistically never).
__device__ __noinline__ void warp_exact_row(
    int row, const int* __restrict__ adjrow,
    const float* __restrict__ h, const float* __restrict__ w,
    float* __restrict__ out, int lane, int N)
{
    float m = -INFINITY;
    for (int j = lane; j < N; j += 32)
        if (adjrow[j] > 0) m = fmaxf(m, g_hw2[j]);
    for (int d = 16; d; d >>= 1) m = fmaxf(m, __shfl_xor_sync(0xffffffffu, m, d));
    bool uni = !(m > -INFINITY);      // fully masked row -> uniform softmax

    float denom = 0.f;
    float4 acc = make_float4(0.f, 0.f, 0.f, 0.f);
    for (int jb = 0; jb < N; jb += 32) {
        int j = jb + lane;
        float wgt = 0.f;
        if (uni) wgt = 1.f;
        else if (adjrow[j] > 0) {
            float e = g_hw2[j];
            if (e >= m - KEEP) wgt = expf(e - m);
        }
        denom += wgt;
        unsigned msk = __ballot_sync(0xffffffffu, wgt != 0.f);
        while (msk) {
            int b = __ffs(msk) - 1;
            msk &= msk - 1;
            float wb = __shfl_sync(0xffffffffu, wgt, b);
            const float* hj = h + (size_t)(jb + b) * NIN;
            float4 d4 = make_float4(0.f, 0.f, 0.f, 0.f);
            for (int k = 0; k < NIN; ++k) {
                float hk = hj[k];  // warp-uniform broadcast load
                float4 wv = *(const float4*)(w + (size_t)k * NOUT + lane * 4);
                d4.x = fmaf(hk, wv.x, d4.x);
                d4.y = fmaf(hk, wv.y, d4.y);
                d4.z = fmaf(hk, wv.z, d4.z);
                d4.w = fmaf(hk, wv.w, d4.w);
            }
            acc.x = fmaf(wb, d4.x, acc.x);
            acc.y = fmaf(wb, d4.y, acc.y);
            acc.z = fmaf(wb, d4.z, acc.z);
            acc.w = fmaf(wb, d4.w, acc.w);
        }
    }
    for (int d = 16; d; d >>= 1) denom += __shfl_xor_sync(0xffffffffu, denom, d);
    float inv = 1.f / denom;
    float4 o = make_float4(acc.x * inv, acc.y * inv, acc.z * inv, acc.w * inv);
    ((float4*)out)[(size_t)row * (NOUT / 4) + lane] = o;
}

__global__ void __launch_bounds__(NT, 1)
gat_persistent(const float* __restrict__ h, const int* __restrict__ adj,
               const float* __restrict__ w, const float* __restrict__ v,
               float* __restrict__ out, int N)
{
    extern __shared__ __align__(16) float dyn[];
    float* s_hwC = dyn;                          // CAP_STAGE * NOUT floats
    float* s_w   = dyn + CAP_STAGE * NOUT;       // [32 warps][2 rows][256 slots]

    __shared__ __align__(16) float s_wv2[NIN];
    __shared__ float s_bmax[32];
    __shared__ int   s_wsum[32], s_woff[32];
    __shared__ int   s_idx[CAP];
    __shared__ float s_e[CAP];
    __shared__ __align__(16) float s_h[64];      // quarter-K slice for D
    __shared__ float s_part[8][NOUT];
    __shared__ int   s_cnt;

    const int t    = threadIdx.x;
    const int lane = t & 31;
    const int wid  = t >> 5;
    const int blk  = blockIdx.x;

    // ---- Issue B's h loads FIRST (DRAM ~600cyc), then do A (L2-bound)
    // while they are in flight; consume them after the syncthreads. ----
    const int row0 = blk * 32 + wid;
    const int row1 = row0 + NB * 32;            // 4736 apart
    const bool v1  = row1 < N;

    const float4* h0 = (const float4*)(h + (size_t)row0 * NIN);
    float4 a0 = h0[lane], b0 = h0[lane + 32];
    float4 a1 = make_float4(0.f, 0.f, 0.f, 0.f), b1 = a1;
    if (v1) {
        const float4* h1 = (const float4*)(h + (size_t)row1 * NIN);
        a1 = h1[lane]; b1 = h1[lane + 32];
    }

    // ---- Phase A: wv2 = w @ v2, redundant per block ----
    {
        int k = t >> 2, part = t & 3;           // 256 k's x 4 partials
        const float4* wr = (const float4*)(w + (size_t)k * NOUT + part * 32);
        const float4* v2 = (const float4*)(v + NOUT + part * 32);
        float p0 = 0.f, p1 = 0.f;
        #pragma unroll
        for (int q = 0; q < 8; ++q) {
            float4 wa = wr[q], va = v2[q];
            p0 = fmaf(wa.x, va.x, p0); p1 = fmaf(wa.y, va.y, p1);
            p0 = fmaf(wa.z, va.z, p0); p1 = fmaf(wa.w, va.w, p1);
        }
        float p = p0 + p1;
        p += __shfl_xor_sync(0xffffffffu, p, 1);
        p += __shfl_xor_sync(0xffffffffu, p, 2);
        if (part == 0) s_wv2[k] = p;
    }
    __syncthreads();

    // ---- Phase B: hw2 for both rows (h already in registers) ----
    {
        const float4* wv = (const float4*)s_wv2;
        float4 wa = wv[lane], wb = wv[lane + 32];
        float acc0 = 0.f, acc1 = 0.f;
        acc0 = fmaf(a0.x, wa.x, acc0); acc1 = fmaf(a1.x, wa.x, acc1);
        acc0 = fmaf(a0.y, wa.y, acc0); acc1 = fmaf(a1.y, wa.y, acc1);
        acc0 = fmaf(a0.z, wa.z, acc0); acc1 = fmaf(a1.z, wa.z, acc1);
        acc0 = fmaf(a0.w, wa.w, acc0); acc1 = fmaf(a1.w, wa.w, acc1);
        acc0 = fmaf(b0.x, wb.x, acc0); acc1 = fmaf(b1.x, wb.x, acc1);
        acc0 = fmaf(b0.y, wb.y, acc0); acc1 = fmaf(b1.y, wb.y, acc1);
        acc0 = fmaf(b0.z, wb.z, acc0); acc1 = fmaf(b1.z, wb.z, acc1);
        acc0 = fmaf(b0.w, wb.w, acc0); acc1 = fmaf(b1.w, wb.w, acc1);
        for (int d = 16; d; d >>= 1) {
            acc0 += __shfl_down_sync(0xffffffffu, acc0, d);
            acc1 += __shfl_down_sync(0xffffffffu, acc1, d);
        }
        if (lane == 0) {
            g_hw2[row0] = acc0;
            float mx = acc0;
            if (v1) { g_hw2[row1] = acc1; mx = fmaxf(mx, acc1); }
            s_bmax[wid] = mx;
        }
        __syncthreads();
        if (wid == 0) {
            float m32 = s_bmax[lane];
            for (int d = 16; d; d >>= 1)
                m32 = fmaxf(m32, __shfl_xor_sync(0xffffffffu, m32, d));
            if (lane == 0) atomicMax(&g_M_key, fkey(m32));
        }
    }
    gbar(NB * 1);

    // ---- Phase C (redundant per block): threshold scan + compaction ----
    float Mthr;
    int   cnt;
    {
        float M   = fkey_inv(g_M_key);
        float thr = M - DELTA_CAND;
        Mthr      = M - (DELTA_CAND - KEEP);

        int j0 = t * 8;                         // N == NT*8
        float4 hva = ((const float4*)g_hw2)[t * 2];
        float4 hvb = ((const float4*)g_hw2)[t * 2 + 1];
        float hv[8] = {hva.x, hva.y, hva.z, hva.w, hvb.x, hvb.y, hvb.z, hvb.w};
        int c = 0;
        #pragma unroll
        for (int r = 0; r < 8; ++r) if (hv[r] >= thr) c++;
        int inc = c;
        for (int d = 1; d < 32; d <<= 1) {
            int vv = __shfl_up_sync(0xffffffffu, inc, d);
            if (lane >= d) inc += vv;
        }
        if (lane == 31) s_wsum[wid] = inc;
        __syncthreads();
        if (wid == 0) {
            int vv = s_wsum[lane];
            int winc = vv;
            for (int d = 1; d < 32; d <<= 1) {
                int u = __shfl_up_sync(0xffffffffu, winc, d);
                if (lane >= d) winc += u;
            }
            s_woff[lane] = winc - vv;
            if (lane == 31) s_cnt = winc;
        }
        __syncthreads();
        cnt = s_cnt;
        if (cnt <= CAP) {
            int pos = s_woff[wid] + (inc - c);
            #pragma unroll
            for (int r = 0; r < 8; ++r) {
                if (hv[r] >= thr) { s_idx[pos] = j0 + r; s_e[pos] = hv[r]; pos++; }
            }
        } else {
            cnt = 0;                            // overflow: every row exact
            Mthr = INFINITY;
        }
        __syncthreads();
    }

    // ---- Phase D (NO barrier): 4*cnt quarter-K GEMV units over 148
    // blocks -> every block does >=1 unit (balanced), then gathers. ----
    {
        int col = t & 127, kg = t >> 7;         // kg in [0,8), 8 k's each
        for (int u = blk; u < 4 * cnt; u += NB) {
            int c = u >> 2, quar = u & 3;
            if (t < 16)
                ((float4*)s_h)[t] =
                    ((const float4*)(h + (size_t)s_idx[c] * NIN + quar * 64))[t];
            __syncthreads();
            const float* wc = w + (size_t)(quar * 64 + kg * 8) * NOUT + col;
            float a0d = 0.f, a1d = 0.f, a2d = 0.f, a3d = 0.f;
            float wv[8];
            #pragma unroll
            for (int q = 0; q < 8; ++q) wv[q] = wc[(size_t)q * NOUT];
            #pragma unroll
            for (int q = 0; q < 8; q += 4) {
                a0d = fmaf(s_h[kg * 8 + q],     wv[q],     a0d);
                a1d = fmaf(s_h[kg * 8 + q + 1], wv[q + 1], a1d);
                a2d = fmaf(s_h[kg * 8 + q + 2], wv[q + 2], a2d);
                a3d = fmaf(s_h[kg * 8 + q + 3], wv[q + 3], a3d);
            }
            s_part[kg][col] = (a0d + a1d) + (a2d + a3d);
            __syncthreads();
            if (t < NOUT) {
                float s = 0.f;
                #pragma unroll
                for (int g = 0; g < 8; ++g) s += s_part[g][t];
                g_hwC[(size_t)u * NOUT + t] = s;   // partial for (c, quar)
            }
            __syncthreads();
        }
    }

    // ---- Phase E-gather: adj gather (__ldcs streaming) + softmax
    // weights for both rows; weights parked in smem across the barrier. ----
    float den0 = 0.f, den1 = 0.f;
    bool  flag0, flag1 = false;
    {
        const int* a0p = adj + (size_t)row0 * N;
        const int* a1p = adj + (size_t)row1 * N;
        float e0[8], e1[8];
        #pragma unroll
        for (int g = 0; g < 8; ++g) {
            int k = g * 32 + lane;
            bool in = k < cnt;
            e0[g] = -INFINITY; e1[g] = -INFINITY;
            if (in) {
                int j = s_idx[k];
                float ee = s_e[k];
                if (__ldcs(a0p + j) > 0) e0[g] = ee;
                if (v1 && __ldcs(a1p + j) > 0) e1[g] = ee;
            }
        }
        // row0
        float m0 = e0[0];
        #pragma unroll
        for (int g = 1; g < 8; ++g) m0 = fmaxf(m0, e0[g]);
        for (int d = 16; d; d >>= 1) m0 = fmaxf(m0, __shfl_xor_sync(0xffffffffu, m0, d));
        bool live0 = m0 > -INFINITY;
        float* sw0 = s_w + (size_t)(wid * 2 + 0) * 256;
        #pragma unroll
        for (int g = 0; g < 8; ++g) {
            float wv = live0 ? __expf(e0[g] - m0) : 0.f;   // -inf -> 0
            den0 += wv;
            sw0[g * 32 + lane] = wv;
        }
        for (int d = 16; d; d >>= 1) den0 += __shfl_xor_sync(0xffffffffu, den0, d);
        flag0 = !(m0 >= Mthr);
        if (flag0) warp_exact_row(row0, a0p, h, w, out, lane, N);
        // row1
        if (v1) {
            float m1 = e1[0];
            #pragma unroll
            for (int g = 1; g < 8; ++g) m1 = fmaxf(m1, e1[g]);
            for (int d = 16; d; d >>= 1) m1 = fmaxf(m1, __shfl_xor_sync(0xffffffffu, m1, d));
            bool live1 = m1 > -INFINITY;
            float* sw1 = s_w + (size_t)(wid * 2 + 1) * 256;
            #pragma unroll
            for (int g = 0; g < 8; ++g) {
                float wv = live1 ? __expf(e1[g] - m1) : 0.f;
                den1 += wv;
                sw1[g * 32 + lane] = wv;
            }
            for (int d = 16; d; d >>= 1) den1 += __shfl_xor_sync(0xffffffffu, den1, d);
            flag1 = !(m1 >= Mthr);
            if (flag1) warp_exact_row(row1, a1p, h, w, out, lane, N);
        }
    }
    gbar(NB * 2);

    // ---- Stage hwC (sum the four quarter-K partials), then accumulate ----
    const int nstage = min(cnt, CAP_STAGE);
    for (int i = t; i < nstage * NOUT; i += NT) {
        int c = i >> 7, col = i & 127;
        s_hwC[i] = (g_hwC[(size_t)(4 * c) * NOUT + col]
                  + g_hwC[(size_t)(4 * c + 1) * NOUT + col])
                 + (g_hwC[(size_t)(4 * c + 2) * NOUT + col]
                  + g_hwC[(size_t)(4 * c + 3) * NOUT + col]);
    }
    __syncthreads();
    {
        const float4* sC4 = (const float4*)s_hwC;
        #pragma unroll
        for (int r = 0; r < 2; ++r) {
            if (r == 1 && !v1) break;
            bool flag = (r == 0) ? flag0 : flag1;
            if (flag) continue;                 // exact path already stored
            int row = (r == 0) ? row0 : row1;
            const float* swr = s_w + (size_t)(wid * 2 + r) * 256;
            float4 acc = make_float4(0.f, 0.f, 0.f, 0.f);
            for (int g = 0; g < 8 && g * 32 < cnt; ++g) {
                float wl = swr[g * 32 + lane];
                unsigned msk = __ballot_sync(0xffffffffu, wl != 0.f);
                while (msk) {
                    int b = __ffs(msk) - 1;
                    msk &= msk - 1;
                    float wb = __shfl_sync(0xffffffffu, wl, b);
                    int c = g * 32 + b;
                    float4 hv;
                    if (c < nstage) {
                        hv = sC4[c * (NOUT / 4) + lane];
                    } else {
                        float4 p0 = ((const float4*)g_hwC)[(size_t)(4 * c) * (NOUT / 4) + lane];
                        float4 p1 = ((const float4*)g_hwC)[(size_t)(4 * c + 1) * (NOUT / 4) + lane];
                        float4 p2 = ((const float4*)g_hwC)[(size_t)(4 * c + 2) * (NOUT / 4) + lane];
                        float4 p3 = ((const float4*)g_hwC)[(size_t)(4 * c + 3) * (NOUT / 4) + lane];
                        hv = make_float4((p0.x + p1.x) + (p2.x + p3.x),
                                         (p0.y + p1.y) + (p2.y + p3.y),
                                         (p0.z + p1.z) + (p2.z + p3.z),
                                         (p0.w + p1.w) + (p2.w + p3.w));
                    }
                    acc.x = fmaf(wb, hv.x, acc.x);
                    acc.y = fmaf(wb, hv.y, acc.y);
                    acc.z = fmaf(wb, hv.z, acc.z);
                    acc.w = fmaf(wb, hv.w, acc.w);
                }
            }
            float den = (r == 0) ? den0 : den1;
            float inv = 1.f / den;
            float4 o = make_float4(acc.x * inv, acc.y * inv, acc.z * inv, acc.w * inv);
            ((float4*)out)[(size_t)row * (NOUT / 4) + lane] = o;
        }
    }

    // ---- Epilogue: last block resets globals for next graph replay ----
    __syncthreads();
    if (t == 0) {
        unsigned r = atomicAdd(&g_done_cnt, 1u);
        if (r == NB - 1) {
            *(volatile unsigned*)&g_M_key    = 0;
            *(volatile unsigned*)&g_done_cnt = 0;
            *(volatile unsigned*)&g_bar_cnt  = 0;
            __threadfence();
        }
    }
}

extern "C" void kernel_launch(void* const* d_in, const int* in_sizes, int n_in,
                              void* d_out, int out_size) {
    const float* h   = (const float*)d_in[0];
    const int*   adj = (const int*)d_in[1];
    const float* w   = (const float*)d_in[2];
    const float* v   = (const float*)d_in[3];
    float* out = (float*)d_out;

    int nout = in_sizes[3] / 2;        // 128
    int nin  = in_sizes[2] / nout;     // 256
    int N    = in_sizes[0] / nin;      // 8192
    (void)nout; (void)nin; (void)n_in; (void)out_size;

    const int dyn_smem = (CAP_STAGE * NOUT + 32 * 2 * 256) * sizeof(float); // 128 KB
    cudaFuncSetAttribute(gat_persistent,
                         cudaFuncAttributeMaxDynamicSharedMemorySize, dyn_smem);
    gat_persistent<<<NB, NT, dyn_smem>>>(h, adj, w, v, out, N);
}

// round 15
// speedup vs baseline: 1.2279x; 1.2279x over previous
#include <cuda_runtime.h>
#include <math.h>
#include <float.h>

// Problem-fixed dims: N=8192, nin=256, nout=128
#define MAXN 8192
#define NIN  256
#define NOUT 128
#define NB   148      // persistent grid: 1 block/SM, co-resident
#define NT   1024

// Candidate window below global max M of hw2 (std ~181, Gumbel scale ~43).
// cnt ~ e^{140/43} ~ 26. Flag margin = DELTA-KEEP = 120 (unchanged across
// rounds): a row is flagged only if it misses ALL ~16 nodes within 120 of M
// (P ~ 1.5e-5/row); flagged rows are recomputed exactly, warp-locally.
// Dropped terms weigh <= e^-20 ~ 2e-9; <=4096 of them -> <=8e-6 relative.
#define DELTA_CAND 140.0f
#define KEEP        20.0f

#define CAP        256    // candidate capacity (cnt>CAP -> all rows exact)
#define CAP_STAGE  128    // candidates staged in dynamic smem for accumulate

// -------- device scratch (no allocations allowed) --------
__device__ float    g_hw2[MAXN];
__device__ unsigned g_M_key;          // ordered-uint encoding of global max
__device__ float    g_hwC[(size_t)CAP * 4 * NOUT];  // quarter-K partials
__device__ unsigned g_bar_cnt;        // zero-init; reset by last block
__device__ unsigned g_done_cnt;

__device__ __forceinline__ unsigned fkey(float f) {
    unsigned b = __float_as_uint(f);
    return b ^ ((b >> 31) ? 0xFFFFFFFFu : 0x80000000u);
}
__device__ __forceinline__ float fkey_inv(unsigned k) {
    unsigned b = (k & 0x80000000u) ? (k ^ 0x80000000u) : ~k;
    return __uint_as_float(b);
}

// Software global barrier: thread 0 arrives + spins, block follows.
__device__ __forceinline__ void gbar(unsigned target) {
    __syncthreads();
    if (threadIdx.x == 0) {
        __threadfence();
        atomicAdd(&g_bar_cnt, 1u);
        while (*(volatile unsigned*)&g_bar_cnt < target) { }
        __threadfence();
    }
    __syncthreads();
}

// Warp-local EXACT recompute of one row (cold path; statistically never).
__device__ __noinline__ void warp_exact_row(
    int row, const int* __restrict__ adjrow,
    const float* __restrict__ h, const float* __restrict__ w,
    float* __restrict__ out, int lane, int N)
{
    float m = -INFINITY;
    for (int j = lane; j < N; j += 32)
        if (adjrow[j] > 0) m = fmaxf(m, g_hw2[j]);
    for (int d = 16; d; d >>= 1) m = fmaxf(m, __shfl_xor_sync(0xffffffffu, m, d));
    bool uni = !(m > -INFINITY);      // fully masked row -> uniform softmax

    float denom = 0.f;
    float4 acc = make_float4(0.f, 0.f, 0.f, 0.f);
    for (int jb = 0; jb < N; jb += 32) {
        int j = jb + lane;
        float wgt = 0.f;
        if (uni) wgt = 1.f;
        else if (adjrow[j] > 0) {
            float e = g_hw2[j];
            if (e >= m - KEEP) wgt = expf(e - m);
        }
        denom += wgt;
        unsigned msk = __ballot_sync(0xffffffffu, wgt != 0.f);
        while (msk) {
            int b = __ffs(msk) - 1;
            msk &= msk - 1;
            float wb = __shfl_sync(0xffffffffu, wgt, b);
            const float* hj = h + (size_t)(jb + b) * NIN;
            float4 d4 = make_float4(0.f, 0.f, 0.f, 0.f);
            for (int k = 0; k < NIN; ++k) {
                float hk = hj[k];  // warp-uniform broadcast load
                float4 wv = *(const float4*)(w + (size_t)k * NOUT + lane * 4);
                d4.x = fmaf(hk, wv.x, d4.x);
                d4.y = fmaf(hk, wv.y, d4.y);
                d4.z = fmaf(hk, wv.z, d4.z);
                d4.w = fmaf(hk, wv.w, d4.w);
            }
            acc.x = fmaf(wb, d4.x, acc.x);
            acc.y = fmaf(wb, d4.y, acc.y);
            acc.z = fmaf(wb, d4.z, acc.z);
            acc.w = fmaf(wb, d4.w, acc.w);
        }
    }
    for (int d = 16; d; d >>= 1) denom += __shfl_xor_sync(0xffffffffu, denom, d);
    float inv = 1.f / denom;
    float4 o = make_float4(acc.x * inv, acc.y * inv, acc.z * inv, acc.w * inv);
    ((float4*)out)[(size_t)row * (NOUT / 4) + lane] = o;
}

__global__ void __launch_bounds__(NT, 1)
gat_persistent(const float* __restrict__ h, const int* __restrict__ adj,
               const float* __restrict__ w, const float* __restrict__ v,
               float* __restrict__ out, int N)
{
    extern __shared__ __align__(16) float s_hwC[];   // CAP_STAGE * NOUT floats

    __shared__ __align__(16) float s_wv2[NIN];
    __shared__ float s_bmax[32];
    __shared__ int   s_wsum[32], s_woff[32];
    __shared__ int   s_idx[CAP];
    __shared__ float s_e[CAP];
    __shared__ __align__(16) float s_h[64];      // quarter-K slice for D
    __shared__ float s_part[8][NOUT];
    __shared__ int   s_cnt;

    const int t    = threadIdx.x;
    const int lane = t & 31;
    const int wid  = t >> 5;
    const int blk  = blockIdx.x;

    // ---- Issue B's h loads FIRST (DRAM ~600cyc), then do A (L2-bound)
    // while they are in flight; consume them after the syncthreads. ----
    const int row0 = blk * 32 + wid;
    const int row1 = row0 + NB * 32;            // 4736 apart
    const bool v1  = row1 < N;

    const float4* h0 = (const float4*)(h + (size_t)row0 * NIN);
    float4 a0 = h0[lane], b0 = h0[lane + 32];
    float4 a1 = make_float4(0.f, 0.f, 0.f, 0.f), b1 = a1;
    if (v1) {
        const float4* h1 = (const float4*)(h + (size_t)row1 * NIN);
        a1 = h1[lane]; b1 = h1[lane + 32];
    }

    // ---- Phase A: wv2 = w @ v2, redundant per block ----
    {
        int k = t >> 2, part = t & 3;           // 256 k's x 4 partials
        const float4* wr = (const float4*)(w + (size_t)k * NOUT + part * 32);
        const float4* v2 = (const float4*)(v + NOUT + part * 32);
        float p0 = 0.f, p1 = 0.f;
        #pragma unroll
        for (int q = 0; q < 8; ++q) {
            float4 wa = wr[q], va = v2[q];
            p0 = fmaf(wa.x, va.x, p0); p1 = fmaf(wa.y, va.y, p1);
            p0 = fmaf(wa.z, va.z, p0); p1 = fmaf(wa.w, va.w, p1);
        }
        float p = p0 + p1;
        p += __shfl_xor_sync(0xffffffffu, p, 1);
        p += __shfl_xor_sync(0xffffffffu, p, 2);
        if (part == 0) s_wv2[k] = p;
    }
    __syncthreads();

    // ---- Phase B: hw2 for both rows (h already in registers) ----
    {
        const float4* wv = (const float4*)s_wv2;
        float4 wa = wv[lane], wb = wv[lane + 32];
        float acc0 = 0.f, acc1 = 0.f;
        acc0 = fmaf(a0.x, wa.x, acc0); acc1 = fmaf(a1.x, wa.x, acc1);
        acc0 = fmaf(a0.y, wa.y, acc0); acc1 = fmaf(a1.y, wa.y, acc1);
        acc0 = fmaf(a0.z, wa.z, acc0); acc1 = fmaf(a1.z, wa.z, acc1);
        acc0 = fmaf(a0.w, wa.w, acc0); acc1 = fmaf(a1.w, wa.w, acc1);
        acc0 = fmaf(b0.x, wb.x, acc0); acc1 = fmaf(b1.x, wb.x, acc1);
        acc0 = fmaf(b0.y, wb.y, acc0); acc1 = fmaf(b1.y, wb.y, acc1);
        acc0 = fmaf(b0.z, wb.z, acc0); acc1 = fmaf(b1.z, wb.z, acc1);
        acc0 = fmaf(b0.w, wb.w, acc0); acc1 = fmaf(b1.w, wb.w, acc1);
        for (int d = 16; d; d >>= 1) {
            acc0 += __shfl_down_sync(0xffffffffu, acc0, d);
            acc1 += __shfl_down_sync(0xffffffffu, acc1, d);
        }
        if (lane == 0) {
            g_hw2[row0] = acc0;
            float mx = acc0;
            if (v1) { g_hw2[row1] = acc1; mx = fmaxf(mx, acc1); }
            s_bmax[wid] = mx;
        }
        __syncthreads();
        if (wid == 0) {
            float m32 = s_bmax[lane];
            for (int d = 16; d; d >>= 1)
                m32 = fmaxf(m32, __shfl_xor_sync(0xffffffffu, m32, d));
            if (lane == 0) atomicMax(&g_M_key, fkey(m32));
        }
    }
    gbar(NB * 1);

    // ---- Phase C (redundant per block): threshold scan + compaction ----
    float Mthr;
    int   cnt;
    {
        float M   = fkey_inv(g_M_key);
        float thr = M - DELTA_CAND;
        Mthr      = M - (DELTA_CAND - KEEP);    // margin 120, as validated

        int j0 = t * 8;                         // N == NT*8
        float4 hva = ((const float4*)g_hw2)[t * 2];
        float4 hvb = ((const float4*)g_hw2)[t * 2 + 1];
        float hv[8] = {hva.x, hva.y, hva.z, hva.w, hvb.x, hvb.y, hvb.z, hvb.w};
        int c = 0;
        #pragma unroll
        for (int r = 0; r < 8; ++r) if (hv[r] >= thr) c++;
        int inc = c;
        for (int d = 1; d < 32; d <<= 1) {
            int vv = __shfl_up_sync(0xffffffffu, inc, d);
            if (lane >= d) inc += vv;
        }
        if (lane == 31) s_wsum[wid] = inc;
        __syncthreads();
        if (wid == 0) {
            int vv = s_wsum[lane];
            int winc = vv;
            for (int d = 1; d < 32; d <<= 1) {
                int u = __shfl_up_sync(0xffffffffu, winc, d);
                if (lane >= d) winc += u;
            }
            s_woff[lane] = winc - vv;
            if (lane == 31) s_cnt = winc;
        }
        __syncthreads();
        cnt = s_cnt;
        if (cnt <= CAP) {
            int pos = s_woff[wid] + (inc - c);
            #pragma unroll
            for (int r = 0; r < 8; ++r) {
                if (hv[r] >= thr) { s_idx[pos] = j0 + r; s_e[pos] = hv[r]; pos++; }
            }
        } else {
            cnt = 0;                            // overflow: every row exact
            Mthr = INFINITY;
        }
        __syncthreads();
    }

    // ---- Phase D (NO barrier): 4*cnt quarter-K GEMV units over 148
    // blocks (cnt~26 -> ~104 units, every block <=1), then gather. ----
    {
        int col = t & 127, kg = t >> 7;         // kg in [0,8), 8 k's each
        for (int u = blk; u < 4 * cnt; u += NB) {
            int c = u >> 2, quar = u & 3;
            if (t < 16)
                ((float4*)s_h)[t] =
                    ((const float4*)(h + (size_t)s_idx[c] * NIN + quar * 64))[t];
            __syncthreads();
            const float* wc = w + (size_t)(quar * 64 + kg * 8) * NOUT + col;
            float a0d = 0.f, a1d = 0.f, a2d = 0.f, a3d = 0.f;
            float wv[8];
            #pragma unroll
            for (int q = 0; q < 8; ++q) wv[q] = wc[(size_t)q * NOUT];
            #pragma unroll
            for (int q = 0; q < 8; q += 4) {
                a0d = fmaf(s_h[kg * 8 + q],     wv[q],     a0d);
                a1d = fmaf(s_h[kg * 8 + q + 1], wv[q + 1], a1d);
                a2d = fmaf(s_h[kg * 8 + q + 2], wv[q + 2], a2d);
                a3d = fmaf(s_h[kg * 8 + q + 3], wv[q + 3], a3d);
            }
            s_part[kg][col] = (a0d + a1d) + (a2d + a3d);
            __syncthreads();
            if (t < NOUT) {
                float s = 0.f;
                #pragma unroll
                for (int g = 0; g < 8; ++g) s += s_part[g][t];
                g_hwC[(size_t)u * NOUT + t] = s;   // partial for (c, quar)
            }
            __syncthreads();
        }
    }

    // ---- Phase E-gather: adj gather + softmax weights for both rows.
    // Weights live in REGISTERS across the barrier (no smem round trip). ----
    float wgt0[8], wgt1[8];
    float den0 = 0.f, den1 = 0.f;
    bool  flag0, flag1 = false;
    {
        const int* a0p = adj + (size_t)row0 * N;
        const int* a1p = adj + (size_t)row1 * N;
        float e0[8], e1[8];
        #pragma unroll
        for (int g = 0; g < 8; ++g) {
            int k = g * 32 + lane;
            bool in = k < cnt;
            e0[g] = -INFINITY; e1[g] = -INFINITY;
            if (in) {
                int j = s_idx[k];
                float ee = s_e[k];
                if (__ldcs(a0p + j) > 0) e0[g] = ee;
                if (v1 && __ldcs(a1p + j) > 0) e1[g] = ee;
            }
        }
        // row0
        float m0 = e0[0];
        #pragma unroll
        for (int g = 1; g < 8; ++g) m0 = fmaxf(m0, e0[g]);
        for (int d = 16; d; d >>= 1) m0 = fmaxf(m0, __shfl_xor_sync(0xffffffffu, m0, d));
        bool live0 = m0 > -INFINITY;
        #pragma unroll
        for (int g = 0; g < 8; ++g) {
            wgt0[g] = live0 ? __expf(e0[g] - m0) : 0.f;   // -inf -> 0
            den0 += wgt0[g];
        }
        for (int d = 16; d; d >>= 1) den0 += __shfl_xor_sync(0xffffffffu, den0, d);
        flag0 = !(m0 >= Mthr);
        if (flag0) warp_exact_row(row0, a0p, h, w, out, lane, N);
        // row1
        if (v1) {
            float m1 = e1[0];
            #pragma unroll
            for (int g = 1; g < 8; ++g) m1 = fmaxf(m1, e1[g]);
            for (int d = 16; d; d >>= 1) m1 = fmaxf(m1, __shfl_xor_sync(0xffffffffu, m1, d));
            bool live1 = m1 > -INFINITY;
            #pragma unroll
            for (int g = 0; g < 8; ++g) {
                wgt1[g] = live1 ? __expf(e1[g] - m1) : 0.f;
                den1 += wgt1[g];
            }
            for (int d = 16; d; d >>= 1) den1 += __shfl_xor_sync(0xffffffffu, den1, d);
            flag1 = !(m1 >= Mthr);
            if (flag1) warp_exact_row(row1, a1p, h, w, out, lane, N);
        } else {
            #pragma unroll
            for (int g = 0; g < 8; ++g) wgt1[g] = 0.f;
        }
    }
    gbar(NB * 2);

    // ---- Stage hwC (sum the four quarter-K partials), then accumulate ----
    const int nstage = min(cnt, CAP_STAGE);
    for (int i = t; i < nstage * NOUT; i += NT) {
        int c = i >> 7, col = i & 127;
        s_hwC[i] = (g_hwC[(size_t)(4 * c) * NOUT + col]
                  + g_hwC[(size_t)(4 * c + 1) * NOUT + col])
                 + (g_hwC[(size_t)(4 * c + 2) * NOUT + col]
                  + g_hwC[(size_t)(4 * c + 3) * NOUT + col]);
    }
    __syncthreads();
    {
        const float4* sC4 = (const float4*)s_hwC;
        #pragma unroll
        for (int r = 0; r < 2; ++r) {
            if (r == 1 && !v1) break;
            bool flag = (r == 0) ? flag0 : flag1;
            if (flag) continue;                 // exact path already stored
            int row = (r == 0) ? row0 : row1;
            float4 acc = make_float4(0.f, 0.f, 0.f, 0.f);
            for (int g = 0; g < 8 && g * 32 < cnt; ++g) {
                float wl = (r == 0) ? wgt0[g] : wgt1[g];
                unsigned msk = __ballot_sync(0xffffffffu, wl != 0.f);
                while (msk) {
                    int b = __ffs(msk) - 1;
                    msk &= msk - 1;
                    float wb = __shfl_sync(0xffffffffu, wl, b);
                    int c = g * 32 + b;
                    float4 hv;
                    if (c < nstage) {
                        hv = sC4[c * (NOUT / 4) + lane];
                    } else {
                        float4 p0 = ((const float4*)g_hwC)[(size_t)(4 * c) * (NOUT / 4) + lane];
                        float4 p1 = ((const float4*)g_hwC)[(size_t)(4 * c + 1) * (NOUT / 4) + lane];
                        float4 p2 = ((const float4*)g_hwC)[(size_t)(4 * c + 2) * (NOUT / 4) + lane];
                        float4 p3 = ((const float4*)g_hwC)[(size_t)(4 * c + 3) * (NOUT / 4) + lane];
                        hv = make_float4((p0.x + p1.x) + (p2.x + p3.x),
                                         (p0.y + p1.y) + (p2.y + p3.y),
                                         (p0.z + p1.z) + (p2.z + p3.z),
                                         (p0.w + p1.w) + (p2.w + p3.w));
                    }
                    acc.x = fmaf(wb, hv.x, acc.x);
                    acc.y = fmaf(wb, hv.y, acc.y);
                    acc.z = fmaf(wb, hv.z, acc.z);
                    acc.w = fmaf(wb, hv.w, acc.w);
                }
            }
            float den = (r == 0) ? den0 : den1;
            float inv = 1.f / den;
            float4 o = make_float4(acc.x * inv, acc.y * inv, acc.z * inv, acc.w * inv);
            ((float4*)out)[(size_t)row * (NOUT / 4) + lane] = o;
        }
    }

    // ---- Epilogue: last block resets globals for next graph replay ----
    __syncthreads();
    if (t == 0) {
        unsigned r = atomicAdd(&g_done_cnt, 1u);
        if (r == NB - 1) {
            *(volatile unsigned*)&g_M_key    = 0;
            *(volatile unsigned*)&g_done_cnt = 0;
            *(volatile unsigned*)&g_bar_cnt  = 0;
            __threadfence();
        }
    }
}

extern "C" void kernel_launch(void* const* d_in, const int* in_sizes, int n_in,
                              void* d_out, int out_size) {
    const float* h   = (const float*)d_in[0];
    const int*   adj = (const int*)d_in[1];
    const float* w   = (const float*)d_in[2];
    const float* v   = (const float*)d_in[3];
    float* out = (float*)d_out;

    int nout = in_sizes[3] / 2;        // 128
    int nin  = in_sizes[2] / nout;     // 256
    int N    = in_sizes[0] / nin;      // 8192
    (void)nout; (void)nin; (void)n_in; (void)out_size;

    const int dyn_smem = CAP_STAGE * NOUT * sizeof(float);  // 64 KB
    cudaFuncSetAttribute(gat_persistent,
                         cudaFuncAttributeMaxDynamicSharedMemorySize, dyn_smem);
    gat_persistent<<<NB, NT, dyn_smem>>>(h, adj, w, v, out, N);
}